// round 16
// baseline (speedup 1.0000x reference)
#include <cuda_runtime.h>
#include <cuda_bf16.h>

// Echo state network, fully fused into ONE kernel.
//   proj = x.reshape(7168,28) @ W_in^T ; h_{t+1} = tanh(proj_t + W_res h_t)
//   h_last[b] = h after step b*28+27 ; out = h_last @ W_out^T + b_out
//
// Scan inner loop is HAND-SCHEDULED with asm volatile: 1 LDS.128 interleaved
// per 2 FFMA2, depth-2-group software pipeline. This stops ptxas from
// clumping the 32 LDS (which pay the nw>=4 effective rt4 LDS floor
// back-to-back = ~128 wasted cycles/step).

#define HIDDEN   128
#define T_STEPS  7168
#define SEQ      28
#define BATCH    256
#define NOUT     10
#define NBLK     112        // T_STEPS / 64

typedef unsigned long long ull;

// +2 zero pad rows (never written) -> unconditional prefetch in the scan
__device__ float g_proj[(T_STEPS + 2) * HIDDEN];
__device__ float g_hlast[BATCH * HIDDEN];
__device__ int   g_sync;

// -------- packed f32x2 helpers (sm_100+) --------
__device__ __forceinline__ ull pack2(float lo, float hi) {
    ull r;
    asm("mov.b64 %0, {%1, %2};" : "=l"(r) : "f"(lo), "f"(hi));
    return r;
}
__device__ __forceinline__ void unpack2(ull v, float& lo, float& hi) {
    asm("mov.b64 {%0, %1}, %2;" : "=f"(lo), "=f"(hi) : "l"(v));
}
__device__ __forceinline__ ull fadd2(ull a, ull b) {
    ull d;
    asm("add.rn.f32x2 %0, %1, %2;" : "=l"(d) : "l"(a), "l"(b));
    return d;
}
__device__ __forceinline__ float tanh_mufu(float x) {
    float y;
    asm("tanh.approx.f32 %0, %1;" : "=f"(y) : "f"(x));
    return y;
}

// ---- order-pinned inner-loop ops (asm volatile => strict program order) ----
#define LDS2V(x, y, addr)                                                \
    asm volatile("ld.shared.v2.u64 {%0, %1}, [%2];"                      \
                 : "=l"(x), "=l"(y) : "r"(addr))
#define FMA2V(acc, wa, hv)                                               \
    asm volatile("fma.rn.f32x2 %0, %1, %2, %0;"                          \
                 : "+l"(acc) : "l"(wa), "l"(hv))

__global__ __launch_bounds__(128, 1) void esn_fused_kernel(
    const float* __restrict__ x,     const float* __restrict__ W_in,
    const float* __restrict__ W_res, const float* __restrict__ W_out,
    const float* __restrict__ b_out, float* __restrict__ out)
{
    __shared__ float sx[64 * SEQ];                 // x tile (proj phase)
    __shared__ __align__(16) float hbuf[2][HIDDEN];

    const int i   = threadIdx.x;
    const int blk = blockIdx.x;

    // ================= Phase 1: proj slice =================
    {
        const int t0 = blk * 64;
        float wi[SEQ];
        #pragma unroll
        for (int d = 0; d < SEQ; d++) wi[d] = __ldg(&W_in[i * SEQ + d]);

        for (int k = i; k < 64 * SEQ; k += 128) sx[k] = x[t0 * SEQ + k];
        __syncthreads();

        #pragma unroll 4
        for (int tl = 0; tl < 64; tl++) {
            const float* xr = &sx[tl * SEQ];       // broadcast
            float a = 0.f;
            #pragma unroll
            for (int d = 0; d < SEQ; d++) a = fmaf(xr[d], wi[d], a);
            g_proj[(t0 + tl) * HIDDEN + i] = a;    // coalesced
        }
    }

    __threadfence();
    __syncthreads();
    if (i == 0) atomicAdd(&g_sync, 1);
    if (blk != 0) return;

    // ============ Block 0: load W_res row (overlaps with the spin) ============
    ull w[64];
    {
        const float2* wrow = (const float2*)(W_res + i * HIDDEN);
        #pragma unroll
        for (int j = 0; j < 64; j++) {
            float2 v = wrow[j];
            w[j] = pack2(v.x, v.y);
        }
    }

    if (i == 0) {
        while (atomicAdd(&g_sync, 0) < NBLK) { }
        atomicExch(&g_sync, 0);                    // reset for next replay
    }
    __syncthreads();
    __threadfence();

    // ================= Phase 2: serial scan =================
    hbuf[0][i] = 0.f;
    __syncthreads();

    const unsigned sb0 = (unsigned)__cvta_generic_to_shared(hbuf[0]);
    const unsigned sb1 = (unsigned)__cvta_generic_to_shared(hbuf[1]);

    float pc = __ldcg(&g_proj[i]);
    float pn = __ldcg(&g_proj[HIDDEN + i]);
    const float* pptr = &g_proj[2 * HIDDEN + i];
    int cnt = 0, batch = 0;

    for (int t = 0; t < T_STEPS; t++) {
        float pf = __ldcg(pptr);                   // pad rows -> no guard
        pptr += HIDDEN;

        const unsigned sa = (t & 1) ? sb1 : sb0;

        // ---- hand-scheduled matvec: depth-2-group pipeline, 1 LDS : 2 FFMA2 ----
        ull hv[3][8];                              // 3 groups in flight
        ull a0 = pack2(pc, 0.f), a1 = 0ull, a2 = 0ull, a3 = 0ull;

        // prologue: groups 0,1
        LDS2V(hv[0][0], hv[0][1], sa +  0);
        LDS2V(hv[0][2], hv[0][3], sa + 16);
        LDS2V(hv[0][4], hv[0][5], sa + 32);
        LDS2V(hv[0][6], hv[0][7], sa + 48);
        LDS2V(hv[1][0], hv[1][1], sa + 64);
        LDS2V(hv[1][2], hv[1][3], sa + 80);
        LDS2V(hv[1][4], hv[1][5], sa + 96);
        LDS2V(hv[1][6], hv[1][7], sa + 112);

        #pragma unroll
        for (int g = 0; g < 8; g++) {
            const int cb = g % 3;                  // consume buffer
            const int lb = (g + 2) % 3;            // load buffer
            const unsigned la = sa + 64 * (g + 2);
            if (g < 6) LDS2V(hv[lb][0], hv[lb][1], la + 0);
            FMA2V(a0, w[8 * g + 0], hv[cb][0]);
            FMA2V(a1, w[8 * g + 1], hv[cb][1]);
            if (g < 6) LDS2V(hv[lb][2], hv[lb][3], la + 16);
            FMA2V(a2, w[8 * g + 2], hv[cb][2]);
            FMA2V(a3, w[8 * g + 3], hv[cb][3]);
            if (g < 6) LDS2V(hv[lb][4], hv[lb][5], la + 32);
            FMA2V(a0, w[8 * g + 4], hv[cb][4]);
            FMA2V(a1, w[8 * g + 5], hv[cb][5]);
            if (g < 6) LDS2V(hv[lb][6], hv[lb][7], la + 48);
            FMA2V(a2, w[8 * g + 6], hv[cb][6]);
            FMA2V(a3, w[8 * g + 7], hv[cb][7]);
        }

        // ---- reduce + native MUFU tanh ----
        ull s01 = fadd2(a0, a1);
        ull s23 = fadd2(a2, a3);
        ull st  = fadd2(s01, s23);
        float lo, hi;
        unpack2(st, lo, hi);
        float hn = tanh_mufu(lo + hi);

        hbuf[(t + 1) & 1][i] = hn;

        if (++cnt == SEQ) {                        // end of batch: record state
            cnt = 0;
            g_hlast[batch * HIDDEN + i] = hn;
            batch++;
        }

        pc = pn;
        pn = pf;
        __syncthreads();
    }

    // ================= Phase 3: output head =================
    __syncthreads();
    for (int e = i; e < BATCH * NOUT; e += 128) {
        int b = e / NOUT;
        int o = e - b * NOUT;
        const float* hr = g_hlast + b * HIDDEN;
        const float* wr = W_out + o * HIDDEN;
        float a = __ldg(&b_out[o]);
        #pragma unroll 8
        for (int h = 0; h < HIDDEN; h++)
            a = fmaf(hr[h], __ldg(&wr[h]), a);
        out[e] = a;
    }
}

extern "C" void kernel_launch(void* const* d_in, const int* in_sizes, int n_in,
                              void* d_out, int out_size)
{
    const float* x     = (const float*)d_in[0];
    const float* W_in  = (const float*)d_in[1];
    const float* W_res = (const float*)d_in[2];
    const float* W_out = (const float*)d_in[3];
    const float* b_out = (const float*)d_in[4];
    float* out = (float*)d_out;

    esn_fused_kernel<<<NBLK, 128>>>(x, W_in, W_res, W_out, b_out, out);
}